// round 12
// baseline (speedup 1.0000x reference)
#include <cuda_runtime.h>
#include <cuda_bf16.h>
#include <math.h>
#include <stdint.h>

#define NHEADS 16
#define NKV 4
#define DH 64
#define NTOK 1024
#define DIM 1024
#define BS 32
#define NW 32
#define JW 33          // MEM + NW
#define NSEL 8
#define NBLK 9         // NSEL + own
#define JTOT 288       // NBLK*BS
#define CDIM 2048
#define HID 2048
#define QKVD 1536
#define PE_SZ (NKV * NW * CDIM)      // 262144
#define HID_SZ (NKV * NW * HID)      // 262144

// ---------------- scratch (static device globals; no runtime alloc) --------
__device__ float g_x[NTOK * DIM];
__device__ float g_qkv[NTOK * QKVD];
__device__ float g_pe[2 * PE_SZ];
__device__ float g_part[8 * HID_SZ];
__device__ float g_hid[2 * HID_SZ];
__device__ float g_craw[2 * NKV * NW * DH];
__device__ float g_ck[NKV * JW * DH];
__device__ float g_cv[NKV * JW * DH];
__device__ float g_csim[NHEADS * NTOK * JW];
__device__ float g_cout[NHEADS * NTOK * DH];
__device__ float g_fout[NHEADS * NTOK * DH];
__device__ int   g_sel[NKV * NTOK * NBLK];
__device__ int   g_msk[NKV * NTOK * NBLK];
__device__ float g_gate[NTOK * 32];
__device__ float g_comb[NTOK * DIM];

__device__ __forceinline__ uint32_t smem_u32(const void* p) {
    uint32_t a;
    asm("{ .reg .u64 t; cvta.to.shared.u64 t, %1; cvt.u32.u64 %0, t; }"
        : "=r"(a) : "l"(p));
    return a;
}

// ============ HMMA (mma.sync m16n8k16 bf16) split-precision GEMM ============
// CTA: 256 threads = 8 warps in 4(m) x 2(n); CTA tile 128 x 64, k-chunk 32.
// A smem stride 40 bf16 (20 u32); B smem stride 72 bf16 (36 u32). Fragment
// loads via ldmatrix (conflict-free for both strides).
#define HS_ABUF 2560           // 128*20 u32
#define HS_BBUF 2304           // 64*36 u32
#define HS_BUF  (2 * HS_ABUF + 2 * HS_BBUF)   // 9728 u32
#define HS_BYTES (2 * HS_BUF * 4)             // 77824 bytes

__device__ __forceinline__ void mma16816(float* c, const uint32_t* a, const uint32_t* b) {
    asm volatile(
        "mma.sync.aligned.m16n8k16.row.col.f32.bf16.bf16.f32 "
        "{%0,%1,%2,%3}, {%4,%5,%6,%7}, {%8,%9}, {%0,%1,%2,%3};\n"
        : "+f"(c[0]), "+f"(c[1]), "+f"(c[2]), "+f"(c[3])
        : "r"(a[0]), "r"(a[1]), "r"(a[2]), "r"(a[3]), "r"(b[0]), "r"(b[1]));
}
__device__ __forceinline__ void ldsm4(uint32_t* r, uint32_t addr) {
    asm volatile("ldmatrix.sync.aligned.m8n8.x4.shared.b16 {%0,%1,%2,%3}, [%4];"
        : "=r"(r[0]), "=r"(r[1]), "=r"(r[2]), "=r"(r[3]) : "r"(addr));
}
__device__ __forceinline__ uint32_t pack_hi(float x, float y) {
    __nv_bfloat162 t(__float2bfloat16(x), __float2bfloat16(y));
    return *(uint32_t*)&t;
}
__device__ __forceinline__ uint32_t pack_lo(float x, float y) {
    __nv_bfloat16 hx = __float2bfloat16(x), hy = __float2bfloat16(y);
    __nv_bfloat162 t(__float2bfloat16(x - __bfloat162float(hx)),
                     __float2bfloat16(y - __bfloat162float(hy)));
    return *(uint32_t*)&t;
}

__device__ __forceinline__ void store_chunkA(uint32_t* Ahi, uint32_t* Alo,
                                             const float4* aR, int tid) {
#pragma unroll
    for (int v = 0; v < 4; v++) {
        int idx = v * 256 + tid; int row = idx >> 3, q = idx & 7;
        uint2 h = make_uint2(pack_hi(aR[v].x, aR[v].y), pack_hi(aR[v].z, aR[v].w));
        uint2 l = make_uint2(pack_lo(aR[v].x, aR[v].y), pack_lo(aR[v].z, aR[v].w));
        *(uint2*)&Ahi[row * 20 + q * 2] = h;
        *(uint2*)&Alo[row * 20 + q * 2] = l;
    }
}
__device__ __forceinline__ void store_chunkB(uint32_t* Bhi, uint32_t* Blo,
                                             const float* bReg, int tid) {
    int n = tid & 63, kh = tid >> 6;
    uint4 h4, l4;
    h4.x = pack_hi(bReg[0], bReg[1]); h4.y = pack_hi(bReg[2], bReg[3]);
    h4.z = pack_hi(bReg[4], bReg[5]); h4.w = pack_hi(bReg[6], bReg[7]);
    l4.x = pack_lo(bReg[0], bReg[1]); l4.y = pack_lo(bReg[2], bReg[3]);
    l4.z = pack_lo(bReg[4], bReg[5]); l4.w = pack_lo(bReg[6], bReg[7]);
    *(uint4*)&((__nv_bfloat16*)Bhi)[n * 72 + kh * 8] = h4;
    *(uint4*)&((__nv_bfloat16*)Blo)[n * 72 + kh * 8] = l4;
}

// C[bm:bm+128, bn:bn+64] = A(.,lda) @ B(.,ldb), fp32 out. K % 32 == 0.
__device__ __forceinline__ void hgemm_body(
    const float* __restrict__ A, int lda,
    const float* __restrict__ B, int ldb,
    float* __restrict__ C, int ldc,
    int K, int bm, int bn)
{
    extern __shared__ uint32_t smu[];
    int tid = threadIdx.x, wid = tid >> 5, lane = tid & 31;
    int mwarp = (wid & 3) * 32;
    int nwarp = (wid >> 2) * 32;
    int r = lane >> 2, cq = lane & 3;
    int bn_n = tid & 63, bn_kh = tid >> 6;

    // ldmatrix per-thread byte offsets
    int i8 = lane & 7;
    int sA1 = (lane >> 3) & 1, sA2 = lane >> 4;
    int sB = lane >> 3;
    uint32_t aOff[2], bOff[2];
#pragma unroll
    for (int ma = 0; ma < 2; ma++)
        aOff[ma] = ((mwarp + ma * 16 + i8 + sA1 * 8) * 40 + sA2 * 8) * 2;
#pragma unroll
    for (int p = 0; p < 2; p++)
        bOff[p] = ((nwarp + p * 16 + i8 + (sB >> 1) * 8) * 72 + (sB & 1) * 8) * 2;
    uint32_t base0 = smem_u32(smu);

    float4 aR[4];
    float bReg[8];
    float acc[2][4][4] = {};

#pragma unroll
    for (int v = 0; v < 4; v++) {
        int idx = v * 256 + tid;
        aR[v] = *(const float4*)&A[(bm + (idx >> 3)) * lda + (idx & 7) * 4];
    }
#pragma unroll
    for (int u = 0; u < 8; u++)
        bReg[u] = B[(bn_kh * 8 + u) * ldb + bn + bn_n];

    int nk = K >> 5;
    int buf = 0;
    store_chunkA(smu, smu + HS_ABUF, aR, tid);
    store_chunkB(smu + 2 * HS_ABUF, smu + 2 * HS_ABUF + HS_BBUF, bReg, tid);
    __syncthreads();

    for (int kt = 0; kt < nk; kt++) {
        if (kt + 1 < nk) {
            int k0 = (kt + 1) << 5;
#pragma unroll
            for (int v = 0; v < 4; v++) {
                int idx = v * 256 + tid;
                aR[v] = *(const float4*)&A[(bm + (idx >> 3)) * lda + k0 + (idx & 7) * 4];
            }
#pragma unroll
            for (int u = 0; u < 8; u++)
                bReg[u] = B[(k0 + bn_kh * 8 + u) * ldb + bn + bn_n];
        }
        uint32_t abuf = base0 + buf * (HS_BUF * 4);
#pragma unroll
        for (int k16 = 0; k16 < 2; k16++) {
            uint32_t kofs = k16 * 32;
            uint32_t ah[2][4], al[2][4], bh[2][4], bl[2][4];
#pragma unroll
            for (int ma = 0; ma < 2; ma++) {
                ldsm4(ah[ma], abuf + aOff[ma] + kofs);
                ldsm4(al[ma], abuf + HS_ABUF * 4 + aOff[ma] + kofs);
            }
#pragma unroll
            for (int p = 0; p < 2; p++) {
                ldsm4(bh[p], abuf + 2 * HS_ABUF * 4 + bOff[p] + kofs);
                ldsm4(bl[p], abuf + 2 * HS_ABUF * 4 + HS_BBUF * 4 + bOff[p] + kofs);
            }
#pragma unroll
            for (int ma = 0; ma < 2; ma++)
#pragma unroll
                for (int na = 0; na < 4; na++) {
                    const uint32_t* bhp = &bh[na >> 1][(na & 1) * 2];
                    const uint32_t* blp = &bl[na >> 1][(na & 1) * 2];
                    mma16816(acc[ma][na], ah[ma], bhp);
                    mma16816(acc[ma][na], ah[ma], blp);
                    mma16816(acc[ma][na], al[ma], bhp);
                }
        }
        if (kt + 1 < nk) {
            uint32_t* nAhi = smu + (buf ^ 1) * HS_BUF;
            store_chunkA(nAhi, nAhi + HS_ABUF, aR, tid);
            store_chunkB(nAhi + 2 * HS_ABUF, nAhi + 2 * HS_ABUF + HS_BBUF, bReg, tid);
            __syncthreads();
            buf ^= 1;
        }
    }
#pragma unroll
    for (int ma = 0; ma < 2; ma++)
#pragma unroll
        for (int na = 0; na < 4; na++) {
            int row = bm + mwarp + ma * 16 + r;
            int col = bn + nwarp + na * 8 + cq * 2;
            *(float2*)&C[row * ldc + col] =
                make_float2(acc[ma][na][0], acc[ma][na][1]);
            *(float2*)&C[(row + 8) * ldc + col] =
                make_float2(acc[ma][na][2], acc[ma][na][3]);
        }
}

__global__ void hgemm_kernel(const float* __restrict__ A, int lda,
                             const float* __restrict__ B, int ldb,
                             float* __restrict__ C, int ldc, int K) {
    hgemm_body(A, lda, B, ldb, C, ldc, K, blockIdx.y * 128, blockIdx.x * 64);
}

__global__ void mlp1_h_kernel(const float* __restrict__ pe,
                              const float* __restrict__ k_w1,
                              const float* __restrict__ v_w1,
                              float* __restrict__ part) {
    int z = blockIdx.z;                  // kv*4 + ks
    int kv = z >> 2, ks = z & 3;
    hgemm_body(pe + kv * PE_SZ + ks * 512, CDIM,
               (kv ? v_w1 : k_w1) + ks * 512 * HID, HID,
               part + z * HID_SZ, HID, 512, 0, blockIdx.x * 64);
}

// ---------------- RMSNorm ---------------------------------------------------
__global__ void rmsnorm_kernel(const float* __restrict__ inp,
                               const float* __restrict__ gw,
                               float* __restrict__ x) {
    int i = blockIdx.x, t = threadIdx.x;
    __shared__ float red[256];
    float s = 0.f;
    for (int d = t; d < DIM; d += 256) { float v = inp[i * DIM + d]; s += v * v; }
    red[t] = s; __syncthreads();
    for (int o = 128; o; o >>= 1) { if (t < o) red[t] += red[t + o]; __syncthreads(); }
    float r = 1.f / sqrtf(red[0] / (float)DIM + 1e-6f);
    for (int d = t; d < DIM; d += 256)
        x[i * DIM + d] = inp[i * DIM + d] * r * gw[d];
}

// reduce split-K partials + bias + relu -> hid
__global__ void mlp1_reduce_kernel(const float* __restrict__ part,
                                   const float* __restrict__ k_b1,
                                   const float* __restrict__ v_b1,
                                   float* __restrict__ hid) {
    int idx = blockIdx.x * 256 + threadIdx.x;   // 2*HID_SZ
    if (idx >= 2 * HID_SZ) return;
    int kv = idx >> 18;
    int rem = idx & (HID_SZ - 1);
    int n = rem & (HID - 1);
    float s = part[(kv * 4 + 0) * HID_SZ + rem] + part[(kv * 4 + 1) * HID_SZ + rem]
            + part[(kv * 4 + 2) * HID_SZ + rem] + part[(kv * 4 + 3) * HID_SZ + rem]
            + (kv ? v_b1[n] : k_b1[n]);
    hid[idx] = fmaxf(s, 0.f);
}

// fused K+V MLP layer 2: 4 rows per CTA (w2 re-use)
__global__ void mlp2_kernel(const float* __restrict__ hid,
                            const float* __restrict__ k_w2,
                            const float* __restrict__ v_w2,
                            const float* __restrict__ k_b2,
                            const float* __restrict__ v_b2,
                            float* __restrict__ craw) {
    int r0 = blockIdx.x * 4, kv = blockIdx.y;
    int tid = threadIdx.x;               // 256
    int col = tid & 63, ks = tid >> 6;
    const float* h0 = hid + kv * HID_SZ + r0 * HID + ks * 512;
    const float* wb = (kv ? v_w2 : k_w2) + ks * 512 * DH + col;
    float acc[4] = {};
#pragma unroll 4
    for (int k = 0; k < 512; k++) {
        float w = wb[k * DH];
        acc[0] += h0[k] * w;
        acc[1] += h0[HID + k] * w;
        acc[2] += h0[2 * HID + k] * w;
        acc[3] += h0[3 * HID + k] * w;
    }
    __shared__ float red[4][256];
#pragma unroll
    for (int j = 0; j < 4; j++) red[j][tid] = acc[j];
    __syncthreads();
    if (ks == 0) {
        float b = (kv ? v_b2[col] : k_b2[col]);
#pragma unroll
        for (int j = 0; j < 4; j++)
            craw[kv * (NKV * NW * DH) + (r0 + j) * DH + col] =
                red[j][col] + red[j][col + 64] + red[j][col + 128]
                + red[j][col + 192] + b;
    }
}

// ---------------- gates: 4 tokens per CTA -----------------------------------
__global__ void gate_kernel(const float* __restrict__ x,
                            const float* __restrict__ gw,
                            const float* __restrict__ gb,
                            float* __restrict__ gate) {
    int i0 = blockIdx.x * 4;
    int tid = threadIdx.x;               // 256
    int col = tid & 31, ks = tid >> 5;
    const float* xr = x + i0 * DIM + ks * 128;
    const float* wb = gw + ks * 128 * 32 + col;
    float acc[4] = {};
#pragma unroll 4
    for (int k = 0; k < 128; k++) {
        float w = wb[k * 32];
        acc[0] += xr[k] * w;
        acc[1] += xr[DIM + k] * w;
        acc[2] += xr[2 * DIM + k] * w;
        acc[3] += xr[3 * DIM + k] * w;
    }
    __shared__ float red[4][256];
#pragma unroll
    for (int j = 0; j < 4; j++) red[j][tid] = acc[j];
    __syncthreads();
    if (tid < 32) {
        float b = gb[col];
#pragma unroll
        for (int j = 0; j < 4; j++) {
            float v = b;
#pragma unroll
            for (int s = 0; s < 8; s++) v += red[j][col + s * 32];
            gate[(i0 + j) * 32 + col] = v;
        }
    }
}

// ---------------- fused build of both compress-MLP inputs -------------------
__global__ void build_pe_kernel(const float* __restrict__ qkv,
                                const float* __restrict__ k_pos,
                                const float* __restrict__ v_pos,
                                float* __restrict__ pe) {
    int idx = blockIdx.x * 256 + threadIdx.x;   // 2*PE_SZ
    if (idx >= 2 * PE_SZ) return;
    int kv = idx >> 18;
    int rem = idx & (PE_SZ - 1);
    int d = rem & 63;
    int t = (rem >> 6) & 31;
    int w = (rem >> 11) & 31;
    int h = rem >> 16;
    const float* pos = kv ? v_pos : k_pos;
    pe[idx] = qkv[(w * BS + t) * QKVD + ((kv ? 20 : 16) + h) * DH + d]
            + pos[(h * BS + t) * DH + d];
}

// ---------------- fused prepend of mem tokens to ck and cv ------------------
__global__ void assemble_c_kernel(const float* __restrict__ craw,
                                  const float* __restrict__ mem_kv,
                                  float* __restrict__ ck,
                                  float* __restrict__ cv) {
    int idx = blockIdx.x * 256 + threadIdx.x;
    if (idx >= 2 * NKV * JW * DH) return;
    int kv = idx / (NKV * JW * DH);
    int rem = idx % (NKV * JW * DH);
    int d = rem & 63;
    int j = (rem >> 6) % JW;
    int h = rem / (JW * DH);
    float* dst = kv ? cv : ck;
    dst[rem] = (j == 0) ? mem_kv[kv * (NKV * DH) + h * DH + d]
                        : craw[kv * (NKV * NW * DH) + (h * NW + (j - 1)) * DH + d];
}

// ---------------- compressed attention, tiled (pre-rotary q) ----------------
__global__ void cattn_kernel(const float* __restrict__ qkv,
                             const float* __restrict__ ck,
                             const float* __restrict__ cv,
                             float* __restrict__ csim_out,
                             float* __restrict__ cout) {
    int i0 = blockIdx.x * 32, head = blockIdx.y, kvh = head >> 2;
    int tid = threadIdx.x;               // 256
    __shared__ float cks[JW][DH + 1];
    __shared__ float cvs[JW][DH + 1];
    __shared__ float qs[32][DH + 1];
    __shared__ float sims[32][JW];
    for (int v = tid; v < JW * DH; v += 256) {
        int j = v >> 6, d = v & 63;
        cks[j][d] = ck[kvh * JW * DH + v];
        cvs[j][d] = cv[kvh * JW * DH + v];
    }
    for (int v = tid; v < 32 * DH; v += 256) {
        int q = v >> 6, d = v & 63;
        qs[q][d] = qkv[(i0 + q) * QKVD + head * DH + d];
    }
    __syncthreads();
    int q = tid >> 3;
    for (int j = tid & 7; j < JW; j += 8) {
        float s = 0.f;
#pragma unroll
        for (int d = 0; d < DH; d++) s += qs[q][d] * cks[j][d];
        s *= 0.125f;
        sims[q][j] = s;
        csim_out[(head * NTOK + i0 + q) * JW + j] = s;
    }
    __syncthreads();
    if (tid < 32) {
        float m = -1e30f;
        for (int j = 0; j < JW; j++) m = fmaxf(m, sims[tid][j]);
        float den = 0.f;
        for (int j = 0; j < JW; j++) { float e = expf(sims[tid][j] - m); sims[tid][j] = e; den += e; }
        float inv = 1.f / den;
        for (int j = 0; j < JW; j++) sims[tid][j] *= inv;
    }
    __syncthreads();
    int d0 = (tid & 7) * 8;
    float acc[8] = {};
    for (int j = 0; j < JW; j++) {
        float p = sims[q][j];
#pragma unroll
        for (int u = 0; u < 8; u++) acc[u] += p * cvs[j][d0 + u];
    }
#pragma unroll
    for (int u = 0; u < 8; u++)
        cout[(head * NTOK + i0 + q) * DH + d0 + u] = acc[u];
}

// ---------------- interleaved rotary on q + k (in-place in qkv) -------------
__global__ void rotary_kernel(float* __restrict__ qkv) {
    int i = blockIdx.x;
    int tid = threadIdx.x;               // 640
    int hh = tid >> 5, p = tid & 31;
    float inv = exp2f(-(float)(2 * p) * (0.015625f * 13.287712379549449f));
    float ang = (float)i * inv;
    float c = cosf(ang), s = sinf(ang);
    float* base = qkv + i * QKVD + hh * DH;
    float x0 = base[2 * p], x1 = base[2 * p + 1];
    base[2 * p]     = x0 * c - x1 * s;
    base[2 * p + 1] = x1 * c + x0 * s;
}

// ---------------- block selection (top-8 + own block) -----------------------
__global__ void select_kernel(const float* __restrict__ csim,
                              int* __restrict__ sel, int* __restrict__ msk) {
    int idx = blockIdx.x * blockDim.x + threadIdx.x;   // NKV*NTOK = 4096
    if (idx >= NKV * NTOK) return;
    int h = idx >> 10, i = idx & 1023;
    float imp[NW];
    for (int w = 0; w < NW; w++) {
        float s = 0.f;
        for (int g = 0; g < 4; g++)
            s += csim[((h * 4 + g) * NTOK + i) * JW + 1 + w];
        imp[w] = s * 0.25f;
    }
    float m = -1000.f;
    for (int w = 0; w < NW; w++) m = fmaxf(m, imp[w]);
    float den = expf(-1000.f - m);
    float p[NW];
    for (int w = 0; w < NW; w++) { p[w] = expf(imp[w] - m); den += p[w]; }
    float inv = 1.f / den;
    bool taken[NW];
    for (int w = 0; w < NW; w++) taken[w] = false;
    for (int s = 0; s < NSEL; s++) {
        int best = 0; float bv = -1.f;
        for (int w = 0; w < NW; w++)
            if (!taken[w] && p[w] > bv) { bv = p[w]; best = w; }
        taken[best] = true;
        sel[idx * NBLK + s] = best;
        msk[idx * NBLK + s] = (bv * inv > 1e-10f) ? 1 : 0;
    }
    sel[idx * NBLK + NSEL] = i >> 5;
    msk[idx * NBLK + NSEL] = 1;
}

// ---------------- fine (block-sparse) attention -----------------------------
__global__ void fattn_kernel(const float* __restrict__ qkv,
                             const int* __restrict__ sel,
                             const int* __restrict__ msk,
                             float* __restrict__ fout) {
    int i = blockIdx.x, kvh = blockIdx.y;
    int tid = threadIdx.x;               // 256
    __shared__ float qs[4][DH];
    __shared__ float kblk[BS][DH + 1];
    __shared__ float sims[4][JTOT];
    __shared__ int ssel[NBLK];
    __shared__ int smask[NBLK];
    __shared__ float gmax[4], ginv[4];
    if (tid < NBLK) {
        ssel[tid]  = sel[(kvh * NTOK + i) * NBLK + tid];
        smask[tid] = msk[(kvh * NTOK + i) * NBLK + tid];
    }
    { int g = tid >> 6, d = tid & 63;
      qs[g][d] = qkv[i * QKVD + (kvh * 4 + g) * DH + d]; }
    __syncthreads();
    for (int b = 0; b < NBLK; b++) {
        int blk = ssel[b];
        for (int l = tid; l < BS * DH / 4; l += 256) {
            int t = l >> 4, dq = (l & 15) * 4;
            float4 v = *(const float4*)&qkv[(blk * BS + t) * QKVD + (16 + kvh) * DH + dq];
            kblk[t][dq] = v.x; kblk[t][dq + 1] = v.y;
            kblk[t][dq + 2] = v.z; kblk[t][dq + 3] = v.w;
        }
        __syncthreads();
        if (tid < 128) {
            int g = tid >> 5, t = tid & 31;
            float s = 0.f;
#pragma unroll
            for (int d = 0; d < DH; d++) s += qs[g][d] * kblk[t][d];
            sims[g][b * BS + t] = smask[b] ? s * 0.125f : -1e30f;
        }
        __syncthreads();
    }
    int w = tid >> 5, lane = tid & 31;
    if (w < 4) {
        float m = -1e30f;
        for (int j = lane; j < JTOT; j += 32) m = fmaxf(m, sims[w][j]);
        for (int o = 16; o; o >>= 1) m = fmaxf(m, __shfl_xor_sync(0xffffffffu, m, o));
        float s = 0.f;
        for (int j = lane; j < JTOT; j += 32) s += expf(sims[w][j] - m);
        for (int o = 16; o; o >>= 1) s += __shfl_xor_sync(0xffffffffu, s, o);
        if (lane == 0) { gmax[w] = m; ginv[w] = 1.f / s; }
    }
    __syncthreads();
    for (int l = tid; l < 4 * JTOT; l += 256) {
        int g = l / JTOT, j = l % JTOT;
        sims[g][j] = expf(sims[g][j] - gmax[g]) * ginv[g];
    }
    __syncthreads();
    // V pass: stage each selected V block in smem (reuse kblk)
    int g = tid >> 6, d = tid & 63;
    float acc = 0.f;
    for (int b = 0; b < NBLK; b++) {
        int blk = ssel[b];
        for (int l = tid; l < BS * DH / 4; l += 256) {
            int t = l >> 4, dq = (l & 15) * 4;
            float4 v = *(const float4*)&qkv[(blk * BS + t) * QKVD + (20 + kvh) * DH + dq];
            kblk[t][dq] = v.x; kblk[t][dq + 1] = v.y;
            kblk[t][dq + 2] = v.z; kblk[t][dq + 3] = v.w;
        }
        __syncthreads();
#pragma unroll
        for (int t = 0; t < BS; t++)
            acc += sims[g][b * BS + t] * kblk[t][d];
        __syncthreads();
    }
    fout[((kvh * 4 + g) * NTOK + i) * DH + d] = acc;
}

// ---------------- sigmoid-gated merge of the two branches -------------------
__global__ void combine_kernel(const float* __restrict__ gate_logits,
                               const float* __restrict__ cout,
                               const float* __restrict__ fout,
                               float* __restrict__ comb) {
    int idx = blockIdx.x * 256 + threadIdx.x;
    if (idx >= NTOK * DIM) return;
    int d = idx & 63, head = (idx >> 6) & 15, i = idx >> 10;
    float l0 = gate_logits[i * 32 + head * 2];
    float l1 = gate_logits[i * 32 + head * 2 + 1];
    float s0 = 1.f / (1.f + expf(-l0));
    float s1 = 1.f / (1.f + expf(-l1));
    comb[idx] = s0 * cout[(head * NTOK + i) * DH + d]
              + s1 * fout[(head * NTOK + i) * DH + d];
}

// ---------------- host launch -----------------------------------------------
extern "C" void kernel_launch(void* const* d_in, const int* in_sizes, int n_in,
                              void* d_out, int out_size) {
    const float* inp    = (const float*)d_in[0];
    const float* g_norm = (const float*)d_in[1];
    const float* w_qkv  = (const float*)d_in[2];
    const float* mem_kv = (const float*)d_in[3];
    const float* k_pos  = (const float*)d_in[4];
    const float* v_pos  = (const float*)d_in[5];
    const float* k_w1   = (const float*)d_in[6];
    const float* k_b1   = (const float*)d_in[7];
    const float* k_w2   = (const float*)d_in[8];
    const float* k_b2   = (const float*)d_in[9];
    const float* v_w1   = (const float*)d_in[10];
    const float* v_b1   = (const float*)d_in[11];
    const float* v_w2   = (const float*)d_in[12];
    const float* v_b2   = (const float*)d_in[13];
    const float* gate_w = (const float*)d_in[14];
    const float* gate_b = (const float*)d_in[15];
    const float* w_out  = (const float*)d_in[16];
    float* out = (float*)d_out;

    float *x, *qkv, *pe, *part, *hid, *craw, *ck, *cv, *csim, *cout, *fout, *gate, *comb;
    int *sel, *msk;
    cudaGetSymbolAddress((void**)&x,    g_x);
    cudaGetSymbolAddress((void**)&qkv,  g_qkv);
    cudaGetSymbolAddress((void**)&pe,   g_pe);
    cudaGetSymbolAddress((void**)&part, g_part);
    cudaGetSymbolAddress((void**)&hid,  g_hid);
    cudaGetSymbolAddress((void**)&craw, g_craw);
    cudaGetSymbolAddress((void**)&ck,   g_ck);
    cudaGetSymbolAddress((void**)&cv,   g_cv);
    cudaGetSymbolAddress((void**)&csim, g_csim);
    cudaGetSymbolAddress((void**)&cout, g_cout);
    cudaGetSymbolAddress((void**)&fout, g_fout);
    cudaGetSymbolAddress((void**)&gate, g_gate);
    cudaGetSymbolAddress((void**)&comb, g_comb);
    cudaGetSymbolAddress((void**)&sel,  g_sel);
    cudaGetSymbolAddress((void**)&msk,  g_msk);

    cudaFuncSetAttribute(hgemm_kernel,
        cudaFuncAttributeMaxDynamicSharedMemorySize, HS_BYTES);
    cudaFuncSetAttribute(mlp1_h_kernel,
        cudaFuncAttributeMaxDynamicSharedMemorySize, HS_BYTES);

    // 1. RMSNorm
    rmsnorm_kernel<<<NTOK, 256>>>(inp, g_norm, x);
    // 2. QKV projection (HMMA): 1024 x 1536 x 1024
    hgemm_kernel<<<dim3(QKVD / 64, NTOK / 128), 256, HS_BYTES>>>(
        x, DIM, w_qkv, QKVD, qkv, QKVD, DIM);
    // 3. fused K+V compress-MLP input
    build_pe_kernel<<<(2 * PE_SZ + 255) / 256, 256>>>(qkv, k_pos, v_pos, pe);
    // 4. fused K+V MLP layer 1 (HMMA, split-K=4) + reduce
    mlp1_h_kernel<<<dim3(HID / 64, 1, 8), 256, HS_BYTES>>>(pe, k_w1, v_w1, part);
    mlp1_reduce_kernel<<<(2 * HID_SZ + 255) / 256, 256>>>(part, k_b1, v_b1, hid);
    // 5. fused K+V MLP layer 2 (4 rows per CTA)
    mlp2_kernel<<<dim3(NKV * NW / 4, 2), 256>>>(hid, k_w2, v_w2, k_b2, v_b2, craw);
    // 6. assemble ck / cv with mem token
    assemble_c_kernel<<<(2 * NKV * JW * DH + 255) / 256, 256>>>(craw, mem_kv, ck, cv);
    // 7. compressed attention, tiled (pre-rotary q)
    cattn_kernel<<<dim3(NTOK / 32, NHEADS), 256>>>(qkv, ck, cv, csim, cout);
    // 8. rotary on q + k (in place)
    rotary_kernel<<<NTOK, 640>>>(qkv);
    // 9. block selection
    select_kernel<<<16, 256>>>(csim, sel, msk);
    // 10. fine block-sparse attention
    fattn_kernel<<<dim3(NTOK, NKV), 256>>>(qkv, sel, msk, fout);
    // 11. gates (4 tokens per CTA)
    gate_kernel<<<NTOK / 4, 256>>>(x, gate_w, gate_b, gate);
    // 12. gated merge
    combine_kernel<<<(NTOK * DIM + 255) / 256, 256>>>(gate, cout, fout, comb);
    // 13. output projection (HMMA): 1024 x 1024 x 1024
    hgemm_kernel<<<dim3(DIM / 64, NTOK / 128), 256, HS_BYTES>>>(
        comb, DIM, w_out, DIM, out, DIM, DIM);
}

// round 13
// speedup vs baseline: 1.0338x; 1.0338x over previous
#include <cuda_runtime.h>
#include <cuda_bf16.h>
#include <math.h>
#include <stdint.h>

#define NHEADS 16
#define NKV 4
#define DH 64
#define NTOK 1024
#define DIM 1024
#define BS 32
#define NW 32
#define JW 33          // MEM + NW
#define NSEL 8
#define NBLK 9         // NSEL + own
#define JTOT 288       // NBLK*BS
#define CDIM 2048
#define HID 2048
#define QKVD 1536
#define PE_SZ (NKV * NW * CDIM)      // 262144
#define HID_SZ (NKV * NW * HID)      // 262144

// ---------------- scratch (static device globals; no runtime alloc) --------
__device__ float g_x[NTOK * DIM];
__device__ float g_qkv[NTOK * QKVD];
__device__ float g_pe[2 * PE_SZ];
__device__ float g_part[8 * HID_SZ];
__device__ float g_hid[2 * HID_SZ];
__device__ float g_craw[2 * NKV * NW * DH];
__device__ float g_ck[NKV * JW * DH];
__device__ float g_cv[NKV * JW * DH];
__device__ float g_csim[NHEADS * NTOK * JW];
__device__ float g_cout[NHEADS * NTOK * DH];
__device__ float g_fout[NHEADS * NTOK * DH];
__device__ int   g_sel[NKV * NTOK * NBLK];
__device__ int   g_msk[NKV * NTOK * NBLK];
__device__ float g_gate[NTOK * 32];
__device__ float g_comb[NTOK * DIM];

__device__ __forceinline__ uint32_t smem_u32(const void* p) {
    uint32_t a;
    asm("{ .reg .u64 t; cvta.to.shared.u64 t, %1; cvt.u32.u64 %0, t; }"
        : "=r"(a) : "l"(p));
    return a;
}
#define CPA16(dst, src) \
    asm volatile("cp.async.ca.shared.global [%0], [%1], 16;" :: "r"(dst), "l"(src))
#define CPA_COMMIT() asm volatile("cp.async.commit_group;" ::: "memory")
#define CPA_WAIT0() asm volatile("cp.async.wait_group 0;" ::: "memory")

// ============ HMMA (mma.sync m16n8k16 bf16) split-precision GEMM ============
#define HS_ABUF 2560           // 128*20 u32
#define HS_BBUF 2304           // 64*36 u32
#define HS_BUF  (2 * HS_ABUF + 2 * HS_BBUF)   // 9728 u32
#define HS_BYTES (2 * HS_BUF * 4)             // 77824 bytes

__device__ __forceinline__ void mma16816(float* c, const uint32_t* a, const uint32_t* b) {
    asm volatile(
        "mma.sync.aligned.m16n8k16.row.col.f32.bf16.bf16.f32 "
        "{%0,%1,%2,%3}, {%4,%5,%6,%7}, {%8,%9}, {%0,%1,%2,%3};\n"
        : "+f"(c[0]), "+f"(c[1]), "+f"(c[2]), "+f"(c[3])
        : "r"(a[0]), "r"(a[1]), "r"(a[2]), "r"(a[3]), "r"(b[0]), "r"(b[1]));
}
__device__ __forceinline__ void ldsm4(uint32_t* r, uint32_t addr) {
    asm volatile("ldmatrix.sync.aligned.m8n8.x4.shared.b16 {%0,%1,%2,%3}, [%4];"
        : "=r"(r[0]), "=r"(r[1]), "=r"(r[2]), "=r"(r[3]) : "r"(addr));
}
__device__ __forceinline__ uint32_t pack_hi(float x, float y) {
    __nv_bfloat162 t(__float2bfloat16(x), __float2bfloat16(y));
    return *(uint32_t*)&t;
}
__device__ __forceinline__ uint32_t pack_lo(float x, float y) {
    __nv_bfloat16 hx = __float2bfloat16(x), hy = __float2bfloat16(y);
    __nv_bfloat162 t(__float2bfloat16(x - __bfloat162float(hx)),
                     __float2bfloat16(y - __bfloat162float(hy)));
    return *(uint32_t*)&t;
}

__device__ __forceinline__ void store_chunkA(uint32_t* Ahi, uint32_t* Alo,
                                             const float4* aR, int tid) {
#pragma unroll
    for (int v = 0; v < 4; v++) {
        int idx = v * 256 + tid; int row = idx >> 3, q = idx & 7;
        uint2 h = make_uint2(pack_hi(aR[v].x, aR[v].y), pack_hi(aR[v].z, aR[v].w));
        uint2 l = make_uint2(pack_lo(aR[v].x, aR[v].y), pack_lo(aR[v].z, aR[v].w));
        *(uint2*)&Ahi[row * 20 + q * 2] = h;
        *(uint2*)&Alo[row * 20 + q * 2] = l;
    }
}
__device__ __forceinline__ void store_chunkB(uint32_t* Bhi, uint32_t* Blo,
                                             const float* bReg, int tid) {
    int n = tid & 63, kh = tid >> 6;
    uint4 h4, l4;
    h4.x = pack_hi(bReg[0], bReg[1]); h4.y = pack_hi(bReg[2], bReg[3]);
    h4.z = pack_hi(bReg[4], bReg[5]); h4.w = pack_hi(bReg[6], bReg[7]);
    l4.x = pack_lo(bReg[0], bReg[1]); l4.y = pack_lo(bReg[2], bReg[3]);
    l4.z = pack_lo(bReg[4], bReg[5]); l4.w = pack_lo(bReg[6], bReg[7]);
    *(uint4*)&((__nv_bfloat16*)Bhi)[n * 72 + kh * 8] = h4;
    *(uint4*)&((__nv_bfloat16*)Blo)[n * 72 + kh * 8] = l4;
}

// C[bm:bm+128, bn:bn+64] = A(.,lda) @ B(.,ldb), fp32 out. K % 32 == 0.
__device__ __forceinline__ void hgemm_body(
    const float* __restrict__ A, int lda,
    const float* __restrict__ B, int ldb,
    float* __restrict__ C, int ldc,
    int K, int bm, int bn)
{
    extern __shared__ uint32_t smu[];
    int tid = threadIdx.x, wid = tid >> 5, lane = tid & 31;
    int mwarp = (wid & 3) * 32;
    int nwarp = (wid >> 2) * 32;
    int r = lane >> 2, cq = lane & 3;
    int bn_n = tid & 63, bn_kh = tid >> 6;

    int i8 = lane & 7;
    int sA1 = (lane >> 3) & 1, sA2 = lane >> 4;
    int sB = lane >> 3;
    uint32_t aOff[2], bOff[2];
#pragma unroll
    for (int ma = 0; ma < 2; ma++)
        aOff[ma] = ((mwarp + ma * 16 + i8 + sA1 * 8) * 40 + sA2 * 8) * 2;
#pragma unroll
    for (int p = 0; p < 2; p++)
        bOff[p] = ((nwarp + p * 16 + i8 + (sB >> 1) * 8) * 72 + (sB & 1) * 8) * 2;
    uint32_t base0 = smem_u32(smu);

    float4 aR[4];
    float bReg[8];
    float acc[2][4][4] = {};

#pragma unroll
    for (int v = 0; v < 4; v++) {
        int idx = v * 256 + tid;
        aR[v] = *(const float4*)&A[(bm + (idx >> 3)) * lda + (idx & 7) * 4];
    }
#pragma unroll
    for (int u = 0; u < 8; u++)
        bReg[u] = B[(bn_kh * 8 + u) * ldb + bn + bn_n];

    int nk = K >> 5;
    int buf = 0;
    store_chunkA(smu, smu + HS_ABUF, aR, tid);
    store_chunkB(smu + 2 * HS_ABUF, smu + 2 * HS_ABUF + HS_BBUF, bReg, tid);
    __syncthreads();

    for (int kt = 0; kt < nk; kt++) {
        if (kt + 1 < nk) {
            int k0 = (kt + 1) << 5;
#pragma unroll
            for (int v = 0; v < 4; v++) {
                int idx = v * 256 + tid;
                aR[v] = *(const float4*)&A[(bm + (idx >> 3)) * lda + k0 + (idx & 7) * 4];
            }
#pragma unroll
            for (int u = 0; u < 8; u++)
                bReg[u] = B[(k0 + bn_kh * 8 + u) * ldb + bn + bn_n];
        }
        uint32_t abuf = base0 + buf * (HS_BUF * 4);
#pragma unroll
        for (int k16 = 0; k16 < 2; k16++) {
            uint32_t kofs = k16 * 32;
            uint32_t ah[2][4], al[2][4], bh[2][4], bl[2][4];
#pragma unroll
            for (int ma = 0; ma < 2; ma++) {
                ldsm4(ah[ma], abuf + aOff[ma] + kofs);
                ldsm4(al[ma], abuf + HS_ABUF * 4 + aOff[ma] + kofs);
            }
#pragma unroll
            for (int p = 0; p < 2; p++) {
                ldsm4(bh[p], abuf + 2 * HS_ABUF * 4 + bOff[p] + kofs);
                ldsm4(bl[p], abuf + 2 * HS_ABUF * 4 + HS_BBUF * 4 + bOff[p] + kofs);
            }
#pragma unroll
            for (int ma = 0; ma < 2; ma++)
#pragma unroll
                for (int na = 0; na < 4; na++) {
                    const uint32_t* bhp = &bh[na >> 1][(na & 1) * 2];
                    const uint32_t* blp = &bl[na >> 1][(na & 1) * 2];
                    mma16816(acc[ma][na], ah[ma], bhp);
                    mma16816(acc[ma][na], ah[ma], blp);
                    mma16816(acc[ma][na], al[ma], bhp);
                }
        }
        if (kt + 1 < nk) {
            uint32_t* nAhi = smu + (buf ^ 1) * HS_BUF;
            store_chunkA(nAhi, nAhi + HS_ABUF, aR, tid);
            store_chunkB(nAhi + 2 * HS_ABUF, nAhi + 2 * HS_ABUF + HS_BBUF, bReg, tid);
            __syncthreads();
            buf ^= 1;
        }
    }
#pragma unroll
    for (int ma = 0; ma < 2; ma++)
#pragma unroll
        for (int na = 0; na < 4; na++) {
            int row = bm + mwarp + ma * 16 + r;
            int col = bn + nwarp + na * 8 + cq * 2;
            *(float2*)&C[row * ldc + col] =
                make_float2(acc[ma][na][0], acc[ma][na][1]);
            *(float2*)&C[(row + 8) * ldc + col] =
                make_float2(acc[ma][na][2], acc[ma][na][3]);
        }
}

__global__ void hgemm_kernel(const float* __restrict__ A, int lda,
                             const float* __restrict__ B, int ldb,
                             float* __restrict__ C, int ldc, int K) {
    hgemm_body(A, lda, B, ldb, C, ldc, K, blockIdx.y * 128, blockIdx.x * 64);
}

__global__ void mlp1_h_kernel(const float* __restrict__ pe,
                              const float* __restrict__ k_w1,
                              const float* __restrict__ v_w1,
                              float* __restrict__ part) {
    int z = blockIdx.z;                  // kv*4 + ks
    int kv = z >> 2, ks = z & 3;
    hgemm_body(pe + kv * PE_SZ + ks * 512, CDIM,
               (kv ? v_w1 : k_w1) + ks * 512 * HID, HID,
               part + z * HID_SZ, HID, 512, 0, blockIdx.x * 64);
}

// ---------------- RMSNorm ---------------------------------------------------
__global__ void rmsnorm_kernel(const float* __restrict__ inp,
                               const float* __restrict__ gw,
                               float* __restrict__ x) {
    int i = blockIdx.x, t = threadIdx.x;
    __shared__ float red[256];
    float s = 0.f;
    for (int d = t; d < DIM; d += 256) { float v = inp[i * DIM + d]; s += v * v; }
    red[t] = s; __syncthreads();
    for (int o = 128; o; o >>= 1) { if (t < o) red[t] += red[t + o]; __syncthreads(); }
    float r = 1.f / sqrtf(red[0] / (float)DIM + 1e-6f);
    for (int d = t; d < DIM; d += 256)
        x[i * DIM + d] = inp[i * DIM + d] * r * gw[d];
}

// reduce split-K partials + bias + relu -> hid
__global__ void mlp1_reduce_kernel(const float* __restrict__ part,
                                   const float* __restrict__ k_b1,
                                   const float* __restrict__ v_b1,
                                   float* __restrict__ hid) {
    int idx = blockIdx.x * 256 + threadIdx.x;   // 2*HID_SZ
    if (idx >= 2 * HID_SZ) return;
    int kv = idx >> 18;
    int rem = idx & (HID_SZ - 1);
    int n = rem & (HID - 1);
    float s = part[(kv * 4 + 0) * HID_SZ + rem] + part[(kv * 4 + 1) * HID_SZ + rem]
            + part[(kv * 4 + 2) * HID_SZ + rem] + part[(kv * 4 + 3) * HID_SZ + rem]
            + (kv ? v_b1[n] : k_b1[n]);
    hid[idx] = fmaxf(s, 0.f);
}

// fused K+V MLP layer 2: 4 rows per CTA (w2 re-use)
__global__ void mlp2_kernel(const float* __restrict__ hid,
                            const float* __restrict__ k_w2,
                            const float* __restrict__ v_w2,
                            const float* __restrict__ k_b2,
                            const float* __restrict__ v_b2,
                            float* __restrict__ craw) {
    int r0 = blockIdx.x * 4, kv = blockIdx.y;
    int tid = threadIdx.x;               // 256
    int col = tid & 63, ks = tid >> 6;
    const float* h0 = hid + kv * HID_SZ + r0 * HID + ks * 512;
    const float* wb = (kv ? v_w2 : k_w2) + ks * 512 * DH + col;
    float acc[4] = {};
#pragma unroll 4
    for (int k = 0; k < 512; k++) {
        float w = wb[k * DH];
        acc[0] += h0[k] * w;
        acc[1] += h0[HID + k] * w;
        acc[2] += h0[2 * HID + k] * w;
        acc[3] += h0[3 * HID + k] * w;
    }
    __shared__ float red[4][256];
#pragma unroll
    for (int j = 0; j < 4; j++) red[j][tid] = acc[j];
    __syncthreads();
    if (ks == 0) {
        float b = (kv ? v_b2[col] : k_b2[col]);
#pragma unroll
        for (int j = 0; j < 4; j++)
            craw[kv * (NKV * NW * DH) + (r0 + j) * DH + col] =
                red[j][col] + red[j][col + 64] + red[j][col + 128]
                + red[j][col + 192] + b;
    }
}

// ---------------- gates: 4 tokens per CTA -----------------------------------
__global__ void gate_kernel(const float* __restrict__ x,
                            const float* __restrict__ gw,
                            const float* __restrict__ gb,
                            float* __restrict__ gate) {
    int i0 = blockIdx.x * 4;
    int tid = threadIdx.x;               // 256
    int col = tid & 31, ks = tid >> 5;
    const float* xr = x + i0 * DIM + ks * 128;
    const float* wb = gw + ks * 128 * 32 + col;
    float acc[4] = {};
#pragma unroll 4
    for (int k = 0; k < 128; k++) {
        float w = wb[k * 32];
        acc[0] += xr[k] * w;
        acc[1] += xr[DIM + k] * w;
        acc[2] += xr[2 * DIM + k] * w;
        acc[3] += xr[3 * DIM + k] * w;
    }
    __shared__ float red[4][256];
#pragma unroll
    for (int j = 0; j < 4; j++) red[j][tid] = acc[j];
    __syncthreads();
    if (tid < 32) {
        float b = gb[col];
#pragma unroll
        for (int j = 0; j < 4; j++) {
            float v = b;
#pragma unroll
            for (int s = 0; s < 8; s++) v += red[j][col + s * 32];
            gate[(i0 + j) * 32 + col] = v;
        }
    }
}

// ---------------- fused build of both compress-MLP inputs -------------------
__global__ void build_pe_kernel(const float* __restrict__ qkv,
                                const float* __restrict__ k_pos,
                                const float* __restrict__ v_pos,
                                float* __restrict__ pe) {
    int idx = blockIdx.x * 256 + threadIdx.x;   // 2*PE_SZ
    if (idx >= 2 * PE_SZ) return;
    int kv = idx >> 18;
    int rem = idx & (PE_SZ - 1);
    int d = rem & 63;
    int t = (rem >> 6) & 31;
    int w = (rem >> 11) & 31;
    int h = rem >> 16;
    const float* pos = kv ? v_pos : k_pos;
    pe[idx] = qkv[(w * BS + t) * QKVD + ((kv ? 20 : 16) + h) * DH + d]
            + pos[(h * BS + t) * DH + d];
}

// ---------------- fused prepend of mem tokens to ck and cv ------------------
__global__ void assemble_c_kernel(const float* __restrict__ craw,
                                  const float* __restrict__ mem_kv,
                                  float* __restrict__ ck,
                                  float* __restrict__ cv) {
    int idx = blockIdx.x * 256 + threadIdx.x;
    if (idx >= 2 * NKV * JW * DH) return;
    int kv = idx / (NKV * JW * DH);
    int rem = idx % (NKV * JW * DH);
    int d = rem & 63;
    int j = (rem >> 6) % JW;
    int h = rem / (JW * DH);
    float* dst = kv ? cv : ck;
    dst[rem] = (j == 0) ? mem_kv[kv * (NKV * DH) + h * DH + d]
                        : craw[kv * (NKV * NW * DH) + (h * NW + (j - 1)) * DH + d];
}

// ---------------- compressed attention, tiled (pre-rotary q) ----------------
__global__ void cattn_kernel(const float* __restrict__ qkv,
                             const float* __restrict__ ck,
                             const float* __restrict__ cv,
                             float* __restrict__ csim_out,
                             float* __restrict__ cout) {
    int i0 = blockIdx.x * 32, head = blockIdx.y, kvh = head >> 2;
    int tid = threadIdx.x;               // 256
    __shared__ float cks[JW][DH + 1];
    __shared__ float cvs[JW][DH + 1];
    __shared__ float qs[32][DH + 1];
    __shared__ float sims[32][JW];
    for (int v = tid; v < JW * DH; v += 256) {
        int j = v >> 6, d = v & 63;
        cks[j][d] = ck[kvh * JW * DH + v];
        cvs[j][d] = cv[kvh * JW * DH + v];
    }
    for (int v = tid; v < 32 * DH; v += 256) {
        int q = v >> 6, d = v & 63;
        qs[q][d] = qkv[(i0 + q) * QKVD + head * DH + d];
    }
    __syncthreads();
    int q = tid >> 3;
    for (int j = tid & 7; j < JW; j += 8) {
        float s = 0.f;
#pragma unroll
        for (int d = 0; d < DH; d++) s += qs[q][d] * cks[j][d];
        s *= 0.125f;
        sims[q][j] = s;
        csim_out[(head * NTOK + i0 + q) * JW + j] = s;
    }
    __syncthreads();
    if (tid < 32) {
        float m = -1e30f;
        for (int j = 0; j < JW; j++) m = fmaxf(m, sims[tid][j]);
        float den = 0.f;
        for (int j = 0; j < JW; j++) { float e = expf(sims[tid][j] - m); sims[tid][j] = e; den += e; }
        float inv = 1.f / den;
        for (int j = 0; j < JW; j++) sims[tid][j] *= inv;
    }
    __syncthreads();
    int d0 = (tid & 7) * 8;
    float acc[8] = {};
    for (int j = 0; j < JW; j++) {
        float p = sims[q][j];
#pragma unroll
        for (int u = 0; u < 8; u++) acc[u] += p * cvs[j][d0 + u];
    }
#pragma unroll
    for (int u = 0; u < 8; u++)
        cout[(head * NTOK + i0 + q) * DH + d0 + u] = acc[u];
}

// ---------------- interleaved rotary on q + k (in-place in qkv) -------------
__global__ void rotary_kernel(float* __restrict__ qkv) {
    int i = blockIdx.x;
    int tid = threadIdx.x;               // 640
    int hh = tid >> 5, p = tid & 31;
    float inv = exp2f(-(float)(2 * p) * (0.015625f * 13.287712379549449f));
    float ang = (float)i * inv;
    float c = cosf(ang), s = sinf(ang);
    float* base = qkv + i * QKVD + hh * DH;
    float x0 = base[2 * p], x1 = base[2 * p + 1];
    base[2 * p]     = x0 * c - x1 * s;
    base[2 * p + 1] = x1 * c + x0 * s;
}

// ---------------- block selection (top-8 + own block) -----------------------
__global__ void select_kernel(const float* __restrict__ csim,
                              int* __restrict__ sel, int* __restrict__ msk) {
    int idx = blockIdx.x * blockDim.x + threadIdx.x;   // NKV*NTOK = 4096
    if (idx >= NKV * NTOK) return;
    int h = idx >> 10, i = idx & 1023;
    float imp[NW];
    for (int w = 0; w < NW; w++) {
        float s = 0.f;
        for (int g = 0; g < 4; g++)
            s += csim[((h * 4 + g) * NTOK + i) * JW + 1 + w];
        imp[w] = s * 0.25f;
    }
    float m = -1000.f;
    for (int w = 0; w < NW; w++) m = fmaxf(m, imp[w]);
    float den = expf(-1000.f - m);
    float p[NW];
    for (int w = 0; w < NW; w++) { p[w] = expf(imp[w] - m); den += p[w]; }
    float inv = 1.f / den;
    bool taken[NW];
    for (int w = 0; w < NW; w++) taken[w] = false;
    for (int s = 0; s < NSEL; s++) {
        int best = 0; float bv = -1.f;
        for (int w = 0; w < NW; w++)
            if (!taken[w] && p[w] > bv) { bv = p[w]; best = w; }
        taken[best] = true;
        sel[idx * NBLK + s] = best;
        msk[idx * NBLK + s] = (bv * inv > 1e-10f) ? 1 : 0;
    }
    sel[idx * NBLK + NSEL] = i >> 5;
    msk[idx * NBLK + NSEL] = 1;
}

// ---------------- fine attention: flash-style online softmax + cp.async -----
#define FROW 68   // 272B row: 16B-aligned; float4 reads stride 17 -> no conflicts
__global__ void fattn_kernel(const float* __restrict__ qkv,
                             const int* __restrict__ sel,
                             const int* __restrict__ msk,
                             float* __restrict__ fout) {
    int i = blockIdx.x, kvh = blockIdx.y;
    int tid = threadIdx.x;               // 256
    __shared__ __align__(16) float qs[4][FROW];
    __shared__ __align__(16) float kbuf[2][BS][FROW];
    __shared__ __align__(16) float vbuf[2][BS][FROW];
    __shared__ float pbuf[4][BS];
    __shared__ float alphas[4];
    __shared__ float dinv[4];
    __shared__ int ssel[NBLK];
    __shared__ int smask[NBLK];
    if (tid < NBLK) {
        ssel[tid]  = sel[(kvh * NTOK + i) * NBLK + tid];
        smask[tid] = msk[(kvh * NTOK + i) * NBLK + tid];
    }
    { int g = tid >> 6, d = tid & 63;
      qs[g][d] = qkv[i * QKVD + (kvh * 4 + g) * DH + d]; }
    int ct = tid >> 3, cd = (tid & 7) * 8;   // cp.async coords: 2 float4 per thread
    __syncthreads();

    // prologue: prefetch block 0
    {
        int blk = ssel[0];
        const float* kp = &qkv[(blk * BS + ct) * QKVD + (16 + kvh) * DH + cd];
        const float* vp = &qkv[(blk * BS + ct) * QKVD + (20 + kvh) * DH + cd];
        uint32_t kd = smem_u32(&kbuf[0][ct][cd]);
        uint32_t vd = smem_u32(&vbuf[0][ct][cd]);
        CPA16(kd, kp); CPA16(kd + 16, kp + 4);
        CPA16(vd, vp); CPA16(vd + 16, vp + 4);
        CPA_COMMIT();
    }

    int g_ = tid >> 6, d_ = tid & 63;
    int w = tid >> 5, lane = tid & 31;
    float m = -1e30f, denom = 0.f;       // live in warps 0-3
    float acc = 0.f;                     // per (g_, d_)
    int bufi = 0;
    for (int b = 0; b < NBLK; b++) {
        CPA_WAIT0();
        __syncthreads();                 // K/V of b ready; prev accum done
        if (w < 4 && smask[b]) {
            float s = 0.f;
#pragma unroll
            for (int dq = 0; dq < DH; dq += 4) {
                float4 kq = *(const float4*)&kbuf[bufi][lane][dq];
                float4 qq = *(const float4*)&qs[w][dq];
                s += qq.x * kq.x + qq.y * kq.y + qq.z * kq.z + qq.w * kq.w;
            }
            s *= 0.125f;
            float mb = s;
#pragma unroll
            for (int o = 16; o; o >>= 1) mb = fmaxf(mb, __shfl_xor_sync(0xffffffffu, mb, o));
            float m_new = fmaxf(m, mb);
            float alpha = expf(m - m_new);
            float p = expf(s - m_new);
            float ps = p;
#pragma unroll
            for (int o = 16; o; o >>= 1) ps += __shfl_xor_sync(0xffffffffu, ps, o);
            denom = denom * alpha + ps;
            m = m_new;
            pbuf[w][lane] = p;
            if (lane == 0) alphas[w] = alpha;
        }
        __syncthreads();                 // pbuf/alphas visible
        // prefetch b+1 (targets bufi^1, last read two iterations ago)
        if (b + 1 < NBLK) {
            int blk = ssel[b + 1];
            const float* kp = &qkv[(blk * BS + ct) * QKVD + (16 + kvh) * DH + cd];
            const float* vp = &qkv[(blk * BS + ct) * QKVD + (20 + kvh) * DH + cd];
            uint32_t kd = smem_u32(&kbuf[bufi ^ 1][ct][cd]);
            uint32_t vd = smem_u32(&vbuf[bufi ^ 1][ct][cd]);
            CPA16(kd, kp); CPA16(kd + 16, kp + 4);
            CPA16(vd, vp); CPA16(vd + 16, vp + 4);
            CPA_COMMIT();
        }
        if (smask[b]) {
            float a = acc * alphas[g_];
#pragma unroll
            for (int t = 0; t < BS; t++)
                a += pbuf[g_][t] * vbuf[bufi][t][d_];
            acc = a;
        }
        bufi ^= 1;
    }
    if (w < 4 && lane == 0) dinv[w] = 1.f / denom;
    __syncthreads();
    fout[((kvh * 4 + g_) * NTOK + i) * DH + d_] = acc * dinv[g_];
}

// ---------------- sigmoid-gated merge of the two branches -------------------
__global__ void combine_kernel(const float* __restrict__ gate_logits,
                               const float* __restrict__ cout,
                               const float* __restrict__ fout,
                               float* __restrict__ comb) {
    int idx = blockIdx.x * 256 + threadIdx.x;
    if (idx >= NTOK * DIM) return;
    int d = idx & 63, head = (idx >> 6) & 15, i = idx >> 10;
    float l0 = gate_logits[i * 32 + head * 2];
    float l1 = gate_logits[i * 32 + head * 2 + 1];
    float s0 = 1.f / (1.f + expf(-l0));
    float s1 = 1.f / (1.f + expf(-l1));
    comb[idx] = s0 * cout[(head * NTOK + i) * DH + d]
              + s1 * fout[(head * NTOK + i) * DH + d];
}

// ---------------- host launch -----------------------------------------------
extern "C" void kernel_launch(void* const* d_in, const int* in_sizes, int n_in,
                              void* d_out, int out_size) {
    const float* inp    = (const float*)d_in[0];
    const float* g_norm = (const float*)d_in[1];
    const float* w_qkv  = (const float*)d_in[2];
    const float* mem_kv = (const float*)d_in[3];
    const float* k_pos  = (const float*)d_in[4];
    const float* v_pos  = (const float*)d_in[5];
    const float* k_w1   = (const float*)d_in[6];
    const float* k_b1   = (const float*)d_in[7];
    const float* k_w2   = (const float*)d_in[8];
    const float* k_b2   = (const float*)d_in[9];
    const float* v_w1   = (const float*)d_in[10];
    const float* v_b1   = (const float*)d_in[11];
    const float* v_w2   = (const float*)d_in[12];
    const float* v_b2   = (const float*)d_in[13];
    const float* gate_w = (const float*)d_in[14];
    const float* gate_b = (const float*)d_in[15];
    const float* w_out  = (const float*)d_in[16];
    float* out = (float*)d_out;

    float *x, *qkv, *pe, *part, *hid, *craw, *ck, *cv, *csim, *cout, *fout, *gate, *comb;
    int *sel, *msk;
    cudaGetSymbolAddress((void**)&x,    g_x);
    cudaGetSymbolAddress((void**)&qkv,  g_qkv);
    cudaGetSymbolAddress((void**)&pe,   g_pe);
    cudaGetSymbolAddress((void**)&part, g_part);
    cudaGetSymbolAddress((void**)&hid,  g_hid);
    cudaGetSymbolAddress((void**)&craw, g_craw);
    cudaGetSymbolAddress((void**)&ck,   g_ck);
    cudaGetSymbolAddress((void**)&cv,   g_cv);
    cudaGetSymbolAddress((void**)&csim, g_csim);
    cudaGetSymbolAddress((void**)&cout, g_cout);
    cudaGetSymbolAddress((void**)&fout, g_fout);
    cudaGetSymbolAddress((void**)&gate, g_gate);
    cudaGetSymbolAddress((void**)&comb, g_comb);
    cudaGetSymbolAddress((void**)&sel,  g_sel);
    cudaGetSymbolAddress((void**)&msk,  g_msk);

    cudaFuncSetAttribute(hgemm_kernel,
        cudaFuncAttributeMaxDynamicSharedMemorySize, HS_BYTES);
    cudaFuncSetAttribute(mlp1_h_kernel,
        cudaFuncAttributeMaxDynamicSharedMemorySize, HS_BYTES);

    // 1. RMSNorm
    rmsnorm_kernel<<<NTOK, 256>>>(inp, g_norm, x);
    // 2. QKV projection (HMMA): 1024 x 1536 x 1024
    hgemm_kernel<<<dim3(QKVD / 64, NTOK / 128), 256, HS_BYTES>>>(
        x, DIM, w_qkv, QKVD, qkv, QKVD, DIM);
    // 3. fused K+V compress-MLP input
    build_pe_kernel<<<(2 * PE_SZ + 255) / 256, 256>>>(qkv, k_pos, v_pos, pe);
    // 4. fused K+V MLP layer 1 (HMMA, split-K=4) + reduce
    mlp1_h_kernel<<<dim3(HID / 64, 1, 8), 256, HS_BYTES>>>(pe, k_w1, v_w1, part);
    mlp1_reduce_kernel<<<(2 * HID_SZ + 255) / 256, 256>>>(part, k_b1, v_b1, hid);
    // 5. fused K+V MLP layer 2 (4 rows per CTA)
    mlp2_kernel<<<dim3(NKV * NW / 4, 2), 256>>>(hid, k_w2, v_w2, k_b2, v_b2, craw);
    // 6. assemble ck / cv with mem token
    assemble_c_kernel<<<(2 * NKV * JW * DH + 255) / 256, 256>>>(craw, mem_kv, ck, cv);
    // 7. compressed attention, tiled (pre-rotary q)
    cattn_kernel<<<dim3(NTOK / 32, NHEADS), 256>>>(qkv, ck, cv, csim, cout);
    // 8. rotary on q + k (in place)
    rotary_kernel<<<NTOK, 640>>>(qkv);
    // 9. block selection
    select_kernel<<<16, 256>>>(csim, sel, msk);
    // 10. fine block-sparse attention (flash-style)
    fattn_kernel<<<dim3(NTOK, NKV), 256>>>(qkv, sel, msk, fout);
    // 11. gates (4 tokens per CTA)
    gate_kernel<<<NTOK / 4, 256>>>(x, gate_w, gate_b, gate);
    // 12. gated merge
    combine_kernel<<<(NTOK * DIM + 255) / 256, 256>>>(gate, cout, fout, comb);
    // 13. output projection (HMMA): 1024 x 1024 x 1024
    hgemm_kernel<<<dim3(DIM / 64, NTOK / 128), 256, HS_BYTES>>>(
        comb, DIM, w_out, DIM, out, DIM, DIM);
}

// round 14
// speedup vs baseline: 1.1599x; 1.1220x over previous
#include <cuda_runtime.h>
#include <cuda_bf16.h>
#include <math.h>
#include <stdint.h>

#define NHEADS 16
#define NKV 4
#define DH 64
#define NTOK 1024
#define DIM 1024
#define BS 32
#define NW 32
#define JW 33          // MEM + NW
#define NSEL 8
#define NBLK 9         // NSEL + own
#define JTOT 288       // NBLK*BS
#define CDIM 2048
#define HID 2048
#define QKVD 1536
#define PE_SZ (NKV * NW * CDIM)      // 262144
#define HID_SZ (NKV * NW * HID)      // 262144

// ---------------- scratch (static device globals; no runtime alloc) --------
__device__ float g_x[NTOK * DIM];
__device__ float g_qkv[NTOK * QKVD];
__device__ float g_pe[2 * PE_SZ];
__device__ float g_part[8 * HID_SZ];
__device__ float g_craw[2 * NKV * NW * DH];
__device__ float g_ck[NKV * JW * DH];
__device__ float g_cv[NKV * JW * DH];
__device__ float g_csim[NHEADS * NTOK * JW];
__device__ float g_cout[NHEADS * NTOK * DH];
__device__ float g_fout[NHEADS * NTOK * DH];
__device__ int   g_sel[NKV * NTOK * NBLK];
__device__ int   g_msk[NKV * NTOK * NBLK];
__device__ float g_gate[NTOK * 32];
__device__ float g_comb[NTOK * DIM];

__device__ __forceinline__ uint32_t smem_u32(const void* p) {
    uint32_t a;
    asm("{ .reg .u64 t; cvta.to.shared.u64 t, %1; cvt.u32.u64 %0, t; }"
        : "=r"(a) : "l"(p));
    return a;
}
#define CPA16(dst, src) \
    asm volatile("cp.async.ca.shared.global [%0], [%1], 16;" :: "r"(dst), "l"(src))
#define CPA_COMMIT() asm volatile("cp.async.commit_group;" ::: "memory")
#define CPA_WAIT0() asm volatile("cp.async.wait_group 0;" ::: "memory")

// ============ HMMA (mma.sync m16n8k16 bf16) split-precision GEMM ============
#define HS_ABUF 2560           // 128*20 u32
#define HS_BBUF 2304           // 64*36 u32
#define HS_BUF  (2 * HS_ABUF + 2 * HS_BBUF)   // 9728 u32
#define HS_BYTES (2 * HS_BUF * 4)             // 77824 bytes

__device__ __forceinline__ void mma16816(float* c, const uint32_t* a, const uint32_t* b) {
    asm volatile(
        "mma.sync.aligned.m16n8k16.row.col.f32.bf16.bf16.f32 "
        "{%0,%1,%2,%3}, {%4,%5,%6,%7}, {%8,%9}, {%0,%1,%2,%3};\n"
        : "+f"(c[0]), "+f"(c[1]), "+f"(c[2]), "+f"(c[3])
        : "r"(a[0]), "r"(a[1]), "r"(a[2]), "r"(a[3]), "r"(b[0]), "r"(b[1]));
}
__device__ __forceinline__ void ldsm4(uint32_t* r, uint32_t addr) {
    asm volatile("ldmatrix.sync.aligned.m8n8.x4.shared.b16 {%0,%1,%2,%3}, [%4];"
        : "=r"(r[0]), "=r"(r[1]), "=r"(r[2]), "=r"(r[3]) : "r"(addr));
}
__device__ __forceinline__ uint32_t pack_hi(float x, float y) {
    __nv_bfloat162 t(__float2bfloat16(x), __float2bfloat16(y));
    return *(uint32_t*)&t;
}
__device__ __forceinline__ uint32_t pack_lo(float x, float y) {
    __nv_bfloat16 hx = __float2bfloat16(x), hy = __float2bfloat16(y);
    __nv_bfloat162 t(__float2bfloat16(x - __bfloat162float(hx)),
                     __float2bfloat16(y - __bfloat162float(hy)));
    return *(uint32_t*)&t;
}

__device__ __forceinline__ void store_chunkA(uint32_t* Ahi, uint32_t* Alo,
                                             const float4* aR, int tid) {
#pragma unroll
    for (int v = 0; v < 4; v++) {
        int idx = v * 256 + tid; int row = idx >> 3, q = idx & 7;
        uint2 h = make_uint2(pack_hi(aR[v].x, aR[v].y), pack_hi(aR[v].z, aR[v].w));
        uint2 l = make_uint2(pack_lo(aR[v].x, aR[v].y), pack_lo(aR[v].z, aR[v].w));
        *(uint2*)&Ahi[row * 20 + q * 2] = h;
        *(uint2*)&Alo[row * 20 + q * 2] = l;
    }
}
__device__ __forceinline__ void store_chunkB(uint32_t* Bhi, uint32_t* Blo,
                                             const float* bReg, int tid) {
    int n = tid & 63, kh = tid >> 6;
    uint4 h4, l4;
    h4.x = pack_hi(bReg[0], bReg[1]); h4.y = pack_hi(bReg[2], bReg[3]);
    h4.z = pack_hi(bReg[4], bReg[5]); h4.w = pack_hi(bReg[6], bReg[7]);
    l4.x = pack_lo(bReg[0], bReg[1]); l4.y = pack_lo(bReg[2], bReg[3]);
    l4.z = pack_lo(bReg[4], bReg[5]); l4.w = pack_lo(bReg[6], bReg[7]);
    *(uint4*)&((__nv_bfloat16*)Bhi)[n * 72 + kh * 8] = h4;
    *(uint4*)&((__nv_bfloat16*)Blo)[n * 72 + kh * 8] = l4;
}

// C[bm:bm+128, bn:bn+64] = A(.,lda) @ B(.,ldb), fp32 out. K % 32 == 0.
__device__ __forceinline__ void hgemm_body(
    const float* __restrict__ A, int lda,
    const float* __restrict__ B, int ldb,
    float* __restrict__ C, int ldc,
    int K, int bm, int bn)
{
    extern __shared__ uint32_t smu[];
    int tid = threadIdx.x, wid = tid >> 5, lane = tid & 31;
    int mwarp = (wid & 3) * 32;
    int nwarp = (wid >> 2) * 32;
    int r = lane >> 2, cq = lane & 3;
    int bn_n = tid & 63, bn_kh = tid >> 6;

    int i8 = lane & 7;
    int sA1 = (lane >> 3) & 1, sA2 = lane >> 4;
    int sB = lane >> 3;
    uint32_t aOff[2], bOff[2];
#pragma unroll
    for (int ma = 0; ma < 2; ma++)
        aOff[ma] = ((mwarp + ma * 16 + i8 + sA1 * 8) * 40 + sA2 * 8) * 2;
#pragma unroll
    for (int p = 0; p < 2; p++)
        bOff[p] = ((nwarp + p * 16 + i8 + (sB >> 1) * 8) * 72 + (sB & 1) * 8) * 2;
    uint32_t base0 = smem_u32(smu);

    float4 aR[4];
    float bReg[8];
    float acc[2][4][4] = {};

#pragma unroll
    for (int v = 0; v < 4; v++) {
        int idx = v * 256 + tid;
        aR[v] = *(const float4*)&A[(bm + (idx >> 3)) * lda + (idx & 7) * 4];
    }
#pragma unroll
    for (int u = 0; u < 8; u++)
        bReg[u] = B[(bn_kh * 8 + u) * ldb + bn + bn_n];

    int nk = K >> 5;
    int buf = 0;
    store_chunkA(smu, smu + HS_ABUF, aR, tid);
    store_chunkB(smu + 2 * HS_ABUF, smu + 2 * HS_ABUF + HS_BBUF, bReg, tid);
    __syncthreads();

    for (int kt = 0; kt < nk; kt++) {
        if (kt + 1 < nk) {
            int k0 = (kt + 1) << 5;
#pragma unroll
            for (int v = 0; v < 4; v++) {
                int idx = v * 256 + tid;
                aR[v] = *(const float4*)&A[(bm + (idx >> 3)) * lda + k0 + (idx & 7) * 4];
            }
#pragma unroll
            for (int u = 0; u < 8; u++)
                bReg[u] = B[(k0 + bn_kh * 8 + u) * ldb + bn + bn_n];
        }
        uint32_t abuf = base0 + buf * (HS_BUF * 4);
#pragma unroll
        for (int k16 = 0; k16 < 2; k16++) {
            uint32_t kofs = k16 * 32;
            uint32_t ah[2][4], al[2][4], bh[2][4], bl[2][4];
#pragma unroll
            for (int ma = 0; ma < 2; ma++) {
                ldsm4(ah[ma], abuf + aOff[ma] + kofs);
                ldsm4(al[ma], abuf + HS_ABUF * 4 + aOff[ma] + kofs);
            }
#pragma unroll
            for (int p = 0; p < 2; p++) {
                ldsm4(bh[p], abuf + 2 * HS_ABUF * 4 + bOff[p] + kofs);
                ldsm4(bl[p], abuf + 2 * HS_ABUF * 4 + HS_BBUF * 4 + bOff[p] + kofs);
            }
#pragma unroll
            for (int ma = 0; ma < 2; ma++)
#pragma unroll
                for (int na = 0; na < 4; na++) {
                    const uint32_t* bhp = &bh[na >> 1][(na & 1) * 2];
                    const uint32_t* blp = &bl[na >> 1][(na & 1) * 2];
                    mma16816(acc[ma][na], ah[ma], bhp);
                    mma16816(acc[ma][na], ah[ma], blp);
                    mma16816(acc[ma][na], al[ma], bhp);
                }
        }
        if (kt + 1 < nk) {
            uint32_t* nAhi = smu + (buf ^ 1) * HS_BUF;
            store_chunkA(nAhi, nAhi + HS_ABUF, aR, tid);
            store_chunkB(nAhi + 2 * HS_ABUF, nAhi + 2 * HS_ABUF + HS_BBUF, bReg, tid);
            __syncthreads();
            buf ^= 1;
        }
    }
#pragma unroll
    for (int ma = 0; ma < 2; ma++)
#pragma unroll
        for (int na = 0; na < 4; na++) {
            int row = bm + mwarp + ma * 16 + r;
            int col = bn + nwarp + na * 8 + cq * 2;
            *(float2*)&C[row * ldc + col] =
                make_float2(acc[ma][na][0], acc[ma][na][1]);
            *(float2*)&C[(row + 8) * ldc + col] =
                make_float2(acc[ma][na][2], acc[ma][na][3]);
        }
}

__global__ void hgemm_kernel(const float* __restrict__ A, int lda,
                             const float* __restrict__ B, int ldb,
                             float* __restrict__ C, int ldc, int K) {
    hgemm_body(A, lda, B, ldb, C, ldc, K, blockIdx.y * 128, blockIdx.x * 64);
}

__global__ void mlp1_h_kernel(const float* __restrict__ pe,
                              const float* __restrict__ k_w1,
                              const float* __restrict__ v_w1,
                              float* __restrict__ part) {
    int z = blockIdx.z;                  // kv*4 + ks
    int kv = z >> 2, ks = z & 3;
    hgemm_body(pe + kv * PE_SZ + ks * 512, CDIM,
               (kv ? v_w1 : k_w1) + ks * 512 * HID, HID,
               part + z * HID_SZ, HID, 512, 0, blockIdx.x * 64);
}

// ---------------- RMSNorm + gates (fused) -----------------------------------
__global__ void rmsnorm_gate_kernel(const float* __restrict__ inp,
                                    const float* __restrict__ gw,
                                    const float* __restrict__ gate_w,
                                    const float* __restrict__ gate_b,
                                    float* __restrict__ x,
                                    float* __restrict__ gate) {
    int i = blockIdx.x, t = threadIdx.x;   // 256 threads
    __shared__ float xs[DIM];
    __shared__ float red[256];
    float s = 0.f;
    for (int d = t; d < DIM; d += 256) { float v = inp[i * DIM + d]; s += v * v; }
    red[t] = s; __syncthreads();
    for (int o = 128; o; o >>= 1) { if (t < o) red[t] += red[t + o]; __syncthreads(); }
    float r = 1.f / sqrtf(red[0] / (float)DIM + 1e-6f);
    for (int d = t; d < DIM; d += 256) {
        float v = inp[i * DIM + d] * r * gw[d];
        x[i * DIM + d] = v;
        xs[d] = v;
    }
    __syncthreads();
    // gates: 32 outputs, 8 k-slices of 128
    int col = t & 31, ks = t >> 5;
    const float* wb = gate_w + ks * 128 * 32 + col;
    float acc = 0.f;
#pragma unroll 8
    for (int k = 0; k < 128; k++) acc += xs[ks * 128 + k] * wb[k * 32];
    __syncthreads();
    red[t] = acc; __syncthreads();
    if (t < 32) {
        float v = gate_b[col];
#pragma unroll
        for (int s2 = 0; s2 < 8; s2++) v += red[col + s2 * 32];
        gate[i * 32 + col] = v;
    }
}

// ---- fused MLP layer 2: split-K reduce + bias + relu staged in smem --------
__global__ void mlp2_fused_kernel(const float* __restrict__ part,
                                  const float* __restrict__ k_b1,
                                  const float* __restrict__ v_b1,
                                  const float* __restrict__ k_w2,
                                  const float* __restrict__ v_w2,
                                  const float* __restrict__ k_b2,
                                  const float* __restrict__ v_b2,
                                  float* __restrict__ craw) {
    int r0 = blockIdx.x * 4, kv = blockIdx.y;
    int tid = threadIdx.x;               // 256
    __shared__ float hid4[4][HID];       // 32 KB
    __shared__ float red[4][256];
    const float* b1 = kv ? v_b1 : k_b1;
    // stage hid rows r0..r0+3: reduce 4 split-K parts + bias + relu
    for (int idx = tid; idx < 4 * HID; idx += 256) {
        int j = idx >> 11, k = idx & (HID - 1);
        int rem = (r0 + j) * HID + k;
        float s = part[(kv * 4 + 0) * HID_SZ + rem]
                + part[(kv * 4 + 1) * HID_SZ + rem]
                + part[(kv * 4 + 2) * HID_SZ + rem]
                + part[(kv * 4 + 3) * HID_SZ + rem] + b1[k];
        hid4[j][k] = fmaxf(s, 0.f);
    }
    __syncthreads();
    int col = tid & 63, ks = tid >> 6;
    const float* wb = (kv ? v_w2 : k_w2) + ks * 512 * DH + col;
    float acc[4] = {};
#pragma unroll 4
    for (int k = 0; k < 512; k++) {
        float w = wb[k * DH];
        int kk = ks * 512 + k;
        acc[0] += hid4[0][kk] * w;
        acc[1] += hid4[1][kk] * w;
        acc[2] += hid4[2][kk] * w;
        acc[3] += hid4[3][kk] * w;
    }
#pragma unroll
    for (int j = 0; j < 4; j++) red[j][tid] = acc[j];
    __syncthreads();
    if (ks == 0) {
        float b = (kv ? v_b2[col] : k_b2[col]);
#pragma unroll
        for (int j = 0; j < 4; j++)
            craw[kv * (NKV * NW * DH) + (r0 + j) * DH + col] =
                red[j][col] + red[j][col + 64] + red[j][col + 128]
                + red[j][col + 192] + b;
    }
}

// ---------------- fused build of both compress-MLP inputs -------------------
__global__ void build_pe_kernel(const float* __restrict__ qkv,
                                const float* __restrict__ k_pos,
                                const float* __restrict__ v_pos,
                                float* __restrict__ pe) {
    int idx = blockIdx.x * 256 + threadIdx.x;   // 2*PE_SZ
    if (idx >= 2 * PE_SZ) return;
    int kv = idx >> 18;
    int rem = idx & (PE_SZ - 1);
    int d = rem & 63;
    int t = (rem >> 6) & 31;
    int w = (rem >> 11) & 31;
    int h = rem >> 16;
    const float* pos = kv ? v_pos : k_pos;
    pe[idx] = qkv[(w * BS + t) * QKVD + ((kv ? 20 : 16) + h) * DH + d]
            + pos[(h * BS + t) * DH + d];
}

// ---------------- fused prepend of mem tokens to ck and cv ------------------
__global__ void assemble_c_kernel(const float* __restrict__ craw,
                                  const float* __restrict__ mem_kv,
                                  float* __restrict__ ck,
                                  float* __restrict__ cv) {
    int idx = blockIdx.x * 256 + threadIdx.x;
    if (idx >= 2 * NKV * JW * DH) return;
    int kv = idx / (NKV * JW * DH);
    int rem = idx % (NKV * JW * DH);
    int d = rem & 63;
    int j = (rem >> 6) % JW;
    int h = rem / (JW * DH);
    float* dst = kv ? cv : ck;
    dst[rem] = (j == 0) ? mem_kv[kv * (NKV * DH) + h * DH + d]
                        : craw[kv * (NKV * NW * DH) + (h * NW + (j - 1)) * DH + d];
}

// ---------------- compressed attention, tiled (pre-rotary q) ----------------
__global__ void cattn_kernel(const float* __restrict__ qkv,
                             const float* __restrict__ ck,
                             const float* __restrict__ cv,
                             float* __restrict__ csim_out,
                             float* __restrict__ cout) {
    int i0 = blockIdx.x * 32, head = blockIdx.y, kvh = head >> 2;
    int tid = threadIdx.x;               // 256
    __shared__ float cks[JW][DH + 1];
    __shared__ float cvs[JW][DH + 1];
    __shared__ float qs[32][DH + 1];
    __shared__ float sims[32][JW];
    for (int v = tid; v < JW * DH; v += 256) {
        int j = v >> 6, d = v & 63;
        cks[j][d] = ck[kvh * JW * DH + v];
        cvs[j][d] = cv[kvh * JW * DH + v];
    }
    for (int v = tid; v < 32 * DH; v += 256) {
        int q = v >> 6, d = v & 63;
        qs[q][d] = qkv[(i0 + q) * QKVD + head * DH + d];
    }
    __syncthreads();
    int q = tid >> 3;
    for (int j = tid & 7; j < JW; j += 8) {
        float s = 0.f;
#pragma unroll
        for (int d = 0; d < DH; d++) s += qs[q][d] * cks[j][d];
        s *= 0.125f;
        sims[q][j] = s;
        csim_out[(head * NTOK + i0 + q) * JW + j] = s;
    }
    __syncthreads();
    if (tid < 32) {
        float m = -1e30f;
        for (int j = 0; j < JW; j++) m = fmaxf(m, sims[tid][j]);
        float den = 0.f;
        for (int j = 0; j < JW; j++) { float e = expf(sims[tid][j] - m); sims[tid][j] = e; den += e; }
        float inv = 1.f / den;
        for (int j = 0; j < JW; j++) sims[tid][j] *= inv;
    }
    __syncthreads();
    int d0 = (tid & 7) * 8;
    float acc[8] = {};
    for (int j = 0; j < JW; j++) {
        float p = sims[q][j];
#pragma unroll
        for (int u = 0; u < 8; u++) acc[u] += p * cvs[j][d0 + u];
    }
#pragma unroll
    for (int u = 0; u < 8; u++)
        cout[(head * NTOK + i0 + q) * DH + d0 + u] = acc[u];
}

// ---------------- interleaved rotary on q + k (in-place in qkv) -------------
__global__ void rotary_kernel(float* __restrict__ qkv) {
    int i = blockIdx.x;
    int tid = threadIdx.x;               // 640
    int hh = tid >> 5, p = tid & 31;
    float inv = exp2f(-(float)(2 * p) * (0.015625f * 13.287712379549449f));
    float ang = (float)i * inv;
    float c = cosf(ang), s = sinf(ang);
    float* base = qkv + i * QKVD + hh * DH;
    float x0 = base[2 * p], x1 = base[2 * p + 1];
    base[2 * p]     = x0 * c - x1 * s;
    base[2 * p + 1] = x1 * c + x0 * s;
}

// ---------------- block selection (top-8 + own block) -----------------------
__global__ void select_kernel(const float* __restrict__ csim,
                              int* __restrict__ sel, int* __restrict__ msk) {
    int idx = blockIdx.x * blockDim.x + threadIdx.x;   // NKV*NTOK = 4096
    if (idx >= NKV * NTOK) return;
    int h = idx >> 10, i = idx & 1023;
    float imp[NW];
    for (int w = 0; w < NW; w++) {
        float s = 0.f;
        for (int g = 0; g < 4; g++)
            s += csim[((h * 4 + g) * NTOK + i) * JW + 1 + w];
        imp[w] = s * 0.25f;
    }
    float m = -1000.f;
    for (int w = 0; w < NW; w++) m = fmaxf(m, imp[w]);
    float den = expf(-1000.f - m);
    float p[NW];
    for (int w = 0; w < NW; w++) { p[w] = expf(imp[w] - m); den += p[w]; }
    float inv = 1.f / den;
    bool taken[NW];
    for (int w = 0; w < NW; w++) taken[w] = false;
    for (int s = 0; s < NSEL; s++) {
        int best = 0; float bv = -1.f;
        for (int w = 0; w < NW; w++)
            if (!taken[w] && p[w] > bv) { bv = p[w]; best = w; }
        taken[best] = true;
        sel[idx * NBLK + s] = best;
        msk[idx * NBLK + s] = (bv * inv > 1e-10f) ? 1 : 0;
    }
    sel[idx * NBLK + NSEL] = i >> 5;
    msk[idx * NBLK + NSEL] = 1;
}

// ---------------- fine attention: flash-style online softmax + cp.async -----
#define FROW 68   // 272B row: 16B-aligned; float4 reads stride 17 -> no conflicts
__global__ void fattn_kernel(const float* __restrict__ qkv,
                             const int* __restrict__ sel,
                             const int* __restrict__ msk,
                             float* __restrict__ fout) {
    int i = blockIdx.x, kvh = blockIdx.y;
    int tid = threadIdx.x;               // 256
    __shared__ __align__(16) float qs[4][FROW];
    __shared__ __align__(16) float kbuf[2][BS][FROW];
    __shared__ __align__(16) float vbuf[2][BS][FROW];
    __shared__ float pbuf[4][BS];
    __shared__ float alphas[4];
    __shared__ float dinv[4];
    __shared__ int ssel[NBLK];
    __shared__ int smask[NBLK];
    if (tid < NBLK) {
        ssel[tid]  = sel[(kvh * NTOK + i) * NBLK + tid];
        smask[tid] = msk[(kvh * NTOK + i) * NBLK + tid];
    }
    { int g = tid >> 6, d = tid & 63;
      qs[g][d] = qkv[i * QKVD + (kvh * 4 + g) * DH + d]; }
    int ct = tid >> 3, cd = (tid & 7) * 8;   // cp.async coords: 2 float4 per thread
    __syncthreads();

    {
        int blk = ssel[0];
        const float* kp = &qkv[(blk * BS + ct) * QKVD + (16 + kvh) * DH + cd];
        const float* vp = &qkv[(blk * BS + ct) * QKVD + (20 + kvh) * DH + cd];
        uint32_t kd = smem_u32(&kbuf[0][ct][cd]);
        uint32_t vd = smem_u32(&vbuf[0][ct][cd]);
        CPA16(kd, kp); CPA16(kd + 16, kp + 4);
        CPA16(vd, vp); CPA16(vd + 16, vp + 4);
        CPA_COMMIT();
    }

    int g_ = tid >> 6, d_ = tid & 63;
    int w = tid >> 5, lane = tid & 31;
    float m = -1e30f, denom = 0.f;
    float acc = 0.f;
    int bufi = 0;
    for (int b = 0; b < NBLK; b++) {
        CPA_WAIT0();
        __syncthreads();
        if (w < 4 && smask[b]) {
            float s = 0.f;
#pragma unroll
            for (int dq = 0; dq < DH; dq += 4) {
                float4 kq = *(const float4*)&kbuf[bufi][lane][dq];
                float4 qq = *(const float4*)&qs[w][dq];
                s += qq.x * kq.x + qq.y * kq.y + qq.z * kq.z + qq.w * kq.w;
            }
            s *= 0.125f;
            float mb = s;
#pragma unroll
            for (int o = 16; o; o >>= 1) mb = fmaxf(mb, __shfl_xor_sync(0xffffffffu, mb, o));
            float m_new = fmaxf(m, mb);
            float alpha = expf(m - m_new);
            float p = expf(s - m_new);
            float ps = p;
#pragma unroll
            for (int o = 16; o; o >>= 1) ps += __shfl_xor_sync(0xffffffffu, ps, o);
            denom = denom * alpha + ps;
            m = m_new;
            pbuf[w][lane] = p;
            if (lane == 0) alphas[w] = alpha;
        }
        __syncthreads();
        if (b + 1 < NBLK) {
            int blk = ssel[b + 1];
            const float* kp = &qkv[(blk * BS + ct) * QKVD + (16 + kvh) * DH + cd];
            const float* vp = &qkv[(blk * BS + ct) * QKVD + (20 + kvh) * DH + cd];
            uint32_t kd = smem_u32(&kbuf[bufi ^ 1][ct][cd]);
            uint32_t vd = smem_u32(&vbuf[bufi ^ 1][ct][cd]);
            CPA16(kd, kp); CPA16(kd + 16, kp + 4);
            CPA16(vd, vp); CPA16(vd + 16, vp + 4);
            CPA_COMMIT();
        }
        if (smask[b]) {
            float a = acc * alphas[g_];
#pragma unroll
            for (int t = 0; t < BS; t++)
                a += pbuf[g_][t] * vbuf[bufi][t][d_];
            acc = a;
        }
        bufi ^= 1;
    }
    if (w < 4 && lane == 0) dinv[w] = 1.f / denom;
    __syncthreads();
    fout[((kvh * 4 + g_) * NTOK + i) * DH + d_] = acc * dinv[g_];
}

// ---------------- sigmoid-gated merge of the two branches -------------------
__global__ void combine_kernel(const float* __restrict__ gate_logits,
                               const float* __restrict__ cout,
                               const float* __restrict__ fout,
                               float* __restrict__ comb) {
    int idx = blockIdx.x * 256 + threadIdx.x;
    if (idx >= NTOK * DIM) return;
    int d = idx & 63, head = (idx >> 6) & 15, i = idx >> 10;
    float l0 = gate_logits[i * 32 + head * 2];
    float l1 = gate_logits[i * 32 + head * 2 + 1];
    float s0 = 1.f / (1.f + expf(-l0));
    float s1 = 1.f / (1.f + expf(-l1));
    comb[idx] = s0 * cout[(head * NTOK + i) * DH + d]
              + s1 * fout[(head * NTOK + i) * DH + d];
}

// ---------------- host launch -----------------------------------------------
extern "C" void kernel_launch(void* const* d_in, const int* in_sizes, int n_in,
                              void* d_out, int out_size) {
    const float* inp    = (const float*)d_in[0];
    const float* g_norm = (const float*)d_in[1];
    const float* w_qkv  = (const float*)d_in[2];
    const float* mem_kv = (const float*)d_in[3];
    const float* k_pos  = (const float*)d_in[4];
    const float* v_pos  = (const float*)d_in[5];
    const float* k_w1   = (const float*)d_in[6];
    const float* k_b1   = (const float*)d_in[7];
    const float* k_w2   = (const float*)d_in[8];
    const float* k_b2   = (const float*)d_in[9];
    const float* v_w1   = (const float*)d_in[10];
    const float* v_b1   = (const float*)d_in[11];
    const float* v_w2   = (const float*)d_in[12];
    const float* v_b2   = (const float*)d_in[13];
    const float* gate_w = (const float*)d_in[14];
    const float* gate_b = (const float*)d_in[15];
    const float* w_out  = (const float*)d_in[16];
    float* out = (float*)d_out;

    float *x, *qkv, *pe, *part, *craw, *ck, *cv, *csim, *cout, *fout, *gate, *comb;
    int *sel, *msk;
    cudaGetSymbolAddress((void**)&x,    g_x);
    cudaGetSymbolAddress((void**)&qkv,  g_qkv);
    cudaGetSymbolAddress((void**)&pe,   g_pe);
    cudaGetSymbolAddress((void**)&part, g_part);
    cudaGetSymbolAddress((void**)&craw, g_craw);
    cudaGetSymbolAddress((void**)&ck,   g_ck);
    cudaGetSymbolAddress((void**)&cv,   g_cv);
    cudaGetSymbolAddress((void**)&csim, g_csim);
    cudaGetSymbolAddress((void**)&cout, g_cout);
    cudaGetSymbolAddress((void**)&fout, g_fout);
    cudaGetSymbolAddress((void**)&gate, g_gate);
    cudaGetSymbolAddress((void**)&comb, g_comb);
    cudaGetSymbolAddress((void**)&sel,  g_sel);
    cudaGetSymbolAddress((void**)&msk,  g_msk);

    cudaFuncSetAttribute(hgemm_kernel,
        cudaFuncAttributeMaxDynamicSharedMemorySize, HS_BYTES);
    cudaFuncSetAttribute(mlp1_h_kernel,
        cudaFuncAttributeMaxDynamicSharedMemorySize, HS_BYTES);

    // 1. RMSNorm + gates (fused)
    rmsnorm_gate_kernel<<<NTOK, 256>>>(inp, g_norm, gate_w, gate_b, x, gate);
    // 2. QKV projection (HMMA): 1024 x 1536 x 1024
    hgemm_kernel<<<dim3(QKVD / 64, NTOK / 128), 256, HS_BYTES>>>(
        x, DIM, w_qkv, QKVD, qkv, QKVD, DIM);
    // 3. fused K+V compress-MLP input
    build_pe_kernel<<<(2 * PE_SZ + 255) / 256, 256>>>(qkv, k_pos, v_pos, pe);
    // 4. fused K+V MLP layer 1 (HMMA, split-K=4)
    mlp1_h_kernel<<<dim3(HID / 64, 1, 8), 256, HS_BYTES>>>(pe, k_w1, v_w1, part);
    // 5. fused MLP layer 2 (split-K reduce + bias + relu + GEMM, 4 rows/CTA)
    mlp2_fused_kernel<<<dim3(NKV * NW / 4, 2), 256>>>(
        part, k_b1, v_b1, k_w2, v_w2, k_b2, v_b2, craw);
    // 6. assemble ck / cv with mem token
    assemble_c_kernel<<<(2 * NKV * JW * DH + 255) / 256, 256>>>(craw, mem_kv, ck, cv);
    // 7. compressed attention, tiled (pre-rotary q)
    cattn_kernel<<<dim3(NTOK / 32, NHEADS), 256>>>(qkv, ck, cv, csim, cout);
    // 8. rotary on q + k (in place)
    rotary_kernel<<<NTOK, 640>>>(qkv);
    // 9. block selection
    select_kernel<<<16, 256>>>(csim, sel, msk);
    // 10. fine block-sparse attention (flash-style)
    fattn_kernel<<<dim3(NTOK, NKV), 256>>>(qkv, sel, msk, fout);
    // 11. gated merge
    combine_kernel<<<(NTOK * DIM + 255) / 256, 256>>>(gate, cout, fout, comb);
    // 12. output projection (HMMA): 1024 x 1024 x 1024
    hgemm_kernel<<<dim3(DIM / 64, NTOK / 128), 256, HS_BYTES>>>(
        comb, DIM, w_out, DIM, out, DIM, DIM);
}